// round 6
// baseline (speedup 1.0000x reference)
#include <cuda_runtime.h>
#include <cuda_bf16.h>

// ---------------------------------------------------------------------------
// CutsSelector collapsed to scalar-per-node form:
//   v = f2@cls ; u = f1@cls ; p = Wd@v ; q = Ws@v
//   r = we.v ; s = g_b.v ; c0 = f_b.cls + cls_b
//   t[n]=x[n].q ; du[n]=x[n].u ; dp[n]=x[n].p
//   per edge: acc64[rep][dst] += enc(t[src] + r*ea)  (ONE u64 L2 red, exact
//     fixed point: bits 0..51 value-sum, bits 52..63 count; 4 replicas)
//   score = du + c0 + (cnt>0 ? dp + sum_v/cnt + s : 0) ; probs = sigmoid
//
// K_setup   (1 x 1024): tiny matvecs -> u,p,q + scalars.
// K_t       (ceil(N/8) x 256): warp/node t,du,dp; zero acc replicas.
// K_edgeout (296 x 1024, smem = N*4): stage t into SMEM, LDS gathers,
//   replicated u64 reds, grid barrier, decode + output.
// ---------------------------------------------------------------------------

#define C 128
#define NODE_CAP 24576
#define NREP 4
#define EO_NBLK  296
#define EO_NTHR  1024

#define ENC_OFFSET 4096
#define ENC_SCALE  262144.0f          /* 2^18 */
#define ENC_INV    (1.0f / 262144.0f)
#define CNT_SHIFT  52

__device__ float  g_vec_u[C];
__device__ float  g_vec_p[C];
__device__ float  g_vec_q[C];
__device__ float  g_scalar_r;
__device__ float  g_scalar_s;
__device__ float  g_scalar_c0;
__device__ float  g_t[NODE_CAP];
__device__ float2 g_ddp[NODE_CAP];                      // {du, dp}
__device__ unsigned long long g_acc64[NREP * NODE_CAP]; // replicated packed acc
__device__ unsigned g_bar2, g_done2;                    // self-resetting barrier

__device__ __forceinline__ float warp_sum(float v) {
    #pragma unroll
    for (int o = 16; o > 0; o >>= 1) v += __shfl_xor_sync(0xffffffffu, v, o);
    return v;
}

// Exact fixed-point edge encoding (validated R5, rel_err 1.3e-7):
// integer part (vi+4096)<<18, fraction round-to-nearest at 2^-18, +1 in count.
__device__ __forceinline__ unsigned long long enc_edge(float v) {
    int   vi  = __float2int_rn(v);
    float fr  = v - (float)vi;                   // exact, |fr| <= 0.5
    int   fri = __float2int_rn(fr * ENC_SCALE);  // exact product (2^18)
    return ((unsigned long long)(unsigned)(vi + ENC_OFFSET) << 18)
         + (unsigned long long)(long long)fri
         + (1ULL << CNT_SHIFT);
}

__device__ __forceinline__ void red_u64(unsigned long long* p,
                                        unsigned long long v) {
    asm volatile("red.global.add.u64 [%0], %1;" :: "l"(p), "l"(v) : "memory");
}

// ============================ K_setup =======================================
__global__ void __launch_bounds__(1024, 1)
setup_kernel(const float* __restrict__ g_w,   // [257,128]
             const float* __restrict__ g_b,   // [128]
             const float* __restrict__ f_w,   // [256,128]
             const float* __restrict__ f_b,   // [128]
             const float* __restrict__ cls_w, // [128]
             const float* __restrict__ cls_b) // [1]
{
    __shared__ float scls[C], sv[C];
    const int tid  = threadIdx.x;
    const int wi   = tid >> 5;
    const int lane = tid & 31;

    if (tid < C) scls[tid] = __ldg(&cls_w[tid]);
    __syncthreads();
    float4 cc = ((const float4*)scls)[lane];

    float4 a[8];
    // Stage 1: 256 dots of f_w rows with cls_w -> u (rows 0..127), v (128..255)
    #pragma unroll
    for (int j = 0; j < 8; j++)
        a[j] = __ldg((const float4*)(f_w + (size_t)(wi * 8 + j) * C) + lane);
    #pragma unroll
    for (int j = 0; j < 8; j++) {
        float part = warp_sum(a[j].x * cc.x + a[j].y * cc.y +
                              a[j].z * cc.z + a[j].w * cc.w);
        if (lane == 0) {
            int d = wi * 8 + j;
            if (d < C) g_vec_u[d] = part;
            else       sv[d - C]  = part;
        }
    }
    __syncthreads();
    float4 vv = ((const float4*)sv)[lane];

    // Stage 2: 256 dots of g_w rows with v -> p (rows 0..127), q (128..255)
    #pragma unroll
    for (int j = 0; j < 8; j++)
        a[j] = __ldg((const float4*)(g_w + (size_t)(wi * 8 + j) * C) + lane);
    #pragma unroll
    for (int j = 0; j < 8; j++) {
        float part = warp_sum(a[j].x * vv.x + a[j].y * vv.y +
                              a[j].z * vv.z + a[j].w * vv.w);
        if (lane == 0) {
            int d = wi * 8 + j;
            if (d < C) g_vec_p[d]     = part;
            else       g_vec_q[d - C] = part;
        }
    }

    // Stage 3 (warp 0): scalars
    if (wi == 0) {
        float r = 0.f, s = 0.f, c = 0.f;
        #pragma unroll
        for (int k = lane; k < C; k += 32) {
            float vk = sv[k];
            r += __ldg(&g_w[2 * C * C + k]) * vk;
            s += __ldg(&g_b[k]) * vk;
            c += __ldg(&f_b[k]) * scls[k];
        }
        r = warp_sum(r); s = warp_sum(s); c = warp_sum(c);
        if (lane == 0) {
            g_scalar_r  = r;
            g_scalar_s  = s;
            g_scalar_c0 = c + __ldg(&cls_b[0]);
        }
    }
}

// ============================ K_t ===========================================
__global__ void __launch_bounds__(256)
t_kernel(const float* __restrict__ x, int N) {
    __shared__ float sq[C], su[C], sp[C];
    if (threadIdx.x < C) {
        sq[threadIdx.x] = g_vec_q[threadIdx.x];
        su[threadIdx.x] = g_vec_u[threadIdx.x];
        sp[threadIdx.x] = g_vec_p[threadIdx.x];
    }
    __syncthreads();

    // Zero accumulator replicas (640K threads >> 4*N entries).
    {
        int gid = blockIdx.x * 256 + threadIdx.x;
        if (gid < NREP * NODE_CAP) g_acc64[gid] = 0ULL;
    }

    int node = (int)((blockIdx.x * 256u + threadIdx.x) >> 5);
    int lane = threadIdx.x & 31;
    if (node >= N) return;

    float4 xv = __ldg((const float4*)(x + (size_t)node * C) + lane);
    float4 qv = ((const float4*)sq)[lane];
    float4 uv = ((const float4*)su)[lane];
    float4 pv = ((const float4*)sp)[lane];

    float dq = xv.x * qv.x + xv.y * qv.y + xv.z * qv.z + xv.w * qv.w;
    float du = xv.x * uv.x + xv.y * uv.y + xv.z * uv.z + xv.w * uv.w;
    float dp = xv.x * pv.x + xv.y * pv.y + xv.z * pv.z + xv.w * pv.w;
    #pragma unroll
    for (int o = 16; o > 0; o >>= 1) {
        dq += __shfl_xor_sync(0xffffffffu, dq, o);
        du += __shfl_xor_sync(0xffffffffu, du, o);
        dp += __shfl_xor_sync(0xffffffffu, dp, o);
    }
    if (lane == 0) {
        g_t[node]   = dq;
        g_ddp[node] = make_float2(du, dp);
    }
}

// ============================ K_edgeout =====================================
__global__ void __launch_bounds__(EO_NTHR, 2)
edgeout_kernel(const void*  __restrict__ eidx,
               const float* __restrict__ ea,
               float* __restrict__ out,
               int N, long long E, int twopart)
{
    extern __shared__ float st[];   // staged t table, N floats
    const int tid  = threadIdx.x;
    const int bid  = blockIdx.x;
    const int nblk = gridDim.x;
    const long long gtid       = (long long)bid * EO_NTHR + tid;
    const long long totThreads = (long long)nblk * EO_NTHR;

    __shared__ int s_is64;

    // index-dtype sniff: int64 nonneg < 2^31 shows zeros at odd int32 slots
    if (tid < 32) {
        const int* p = (const int*)eidx;
        int lane = tid;
        int ok = (p[2 * lane + 1] == 0) &&
                 (p[2 * (lane + 32) + 1] == 0) &&
                 (p[2 * (lane + 64) + 1] == 0);
        unsigned b = __ballot_sync(0xffffffffu, ok);
        if (lane == 0) s_is64 = (b == 0xffffffffu) ? 1 : 0;
    }

    // Stage t into SMEM (coalesced float4 + scalar tail).
    {
        const int n4 = N >> 2;
        const float4* t4 = (const float4*)g_t;
        float4* s4 = (float4*)st;
        for (int i = tid; i < n4; i += EO_NTHR) s4[i] = t4[i];
        for (int i = (n4 << 2) + tid; i < N; i += EO_NTHR) st[i] = g_t[i];
    }
    __syncthreads();

    // ---- phase 0: edge scatter (LDS gather + ONE replicated u64 red) ----
    {
        const float rs = g_scalar_r;
        unsigned long long* acc = g_acc64 + (size_t)(bid & (NREP - 1)) * NODE_CAP;
        const long long half = E >> 1;
        if (s_is64) {
            const longlong2* p0 = (const longlong2*)eidx;
            const longlong2* p1 = (const longlong2*)((const long long*)eidx + E);
            const float2*    a2 = (const float2*)ea;
            for (long long i = gtid; i < half; i += totThreads) {
                longlong2 sr = p0[i];
                longlong2 ds = p1[i];
                float2    e2 = a2[i];
                float v0 = st[sr.x] + e2.x * rs;
                float v1 = st[sr.y] + e2.y * rs;
                red_u64(&acc[ds.x], enc_edge(v0));
                red_u64(&acc[ds.y], enc_edge(v1));
            }
            if ((E & 1) && gtid == 0) {
                const long long* p = (const long long*)eidx;
                long long src = p[E - 1], dst = p[2 * E - 1];
                red_u64(&acc[dst], enc_edge(st[src] + ea[E - 1] * rs));
            }
        } else {
            const int2*   p0 = (const int2*)eidx;
            const int2*   p1 = (const int2*)((const int*)eidx + E);
            const float2* a2 = (const float2*)ea;
            for (long long i = gtid; i < half; i += totThreads) {
                int2   sr = p0[i];
                int2   ds = p1[i];
                float2 e2 = a2[i];
                float v0 = st[sr.x] + e2.x * rs;
                float v1 = st[sr.y] + e2.y * rs;
                red_u64(&acc[ds.x], enc_edge(v0));
                red_u64(&acc[ds.y], enc_edge(v1));
            }
            if ((E & 1) && gtid == 0) {
                const int* p = (const int*)eidx;
                int src = p[E - 1], dst = p[2 * E - 1];
                red_u64(&acc[dst], enc_edge(st[src] + ea[E - 1] * rs));
            }
        }
    }

    // ---- grid barrier (drains reds; grid fully resident: 296 = 148 x 2) ----
    __syncthreads();
    if (tid == 0) {
        __threadfence();
        atomicAdd(&g_bar2, 1u);
        unsigned v;
        do {
            asm volatile("ld.global.acquire.gpu.u32 %0, [%1];"
                         : "=r"(v) : "l"(&g_bar2));
        } while (v < (unsigned)nblk);
    }
    __syncthreads();

    // ---- phase 1: decode (sum replicas) + output ----
    {
        const float ss = g_scalar_s;
        const float c0 = g_scalar_c0;
        for (long long n = gtid; n < N; n += totThreads) {
            unsigned long long acc = g_acc64[n]
                                   + g_acc64[NODE_CAP + n]
                                   + g_acc64[2 * NODE_CAP + n]
                                   + g_acc64[3 * NODE_CAP + n];
            unsigned cnt = (unsigned)(acc >> CNT_SHIFT);
            unsigned long long raw = acc & ((1ULL << CNT_SHIFT) - 1ULL);
            float2 ddp = g_ddp[n];
            float score = ddp.x + c0;
            if (cnt > 0u) {
                // hi, lo and 4096*cnt are exact integers < 2^24 in fp32.
                float hi = (float)(long long)(raw >> 18);
                float lo = (float)(int)(raw & 0x3FFFFULL);
                float sum_v = (hi - (float)ENC_OFFSET * (float)cnt)
                            + lo * ENC_INV;
                score += ddp.y + sum_v / (float)cnt + ss;
            }
            float pr = 1.0f / (1.0f + __expf(-score));
            if (twopart) {
                out[n]     = (pr > 0.5f) ? 1.0f : 0.0f;
                out[N + n] = pr;
            } else {
                out[n] = pr;
            }
        }
    }

    // ---- self-reset barrier counters for graph replay ----
    __syncthreads();
    if (tid == 0) {
        __threadfence();
        unsigned old = atomicAdd(&g_done2, 1u);
        if (old == (unsigned)nblk - 1u) {
            g_bar2  = 0u;
            g_done2 = 0u;
            __threadfence();
        }
    }
}

extern "C" void kernel_launch(void* const* d_in, const int* in_sizes, int n_in,
                              void* d_out, int out_size) {
    // metadata order: x_a, edge_index, edge_attr, g_w, g_b, f_w, f_b, cls_w, cls_b
    const float* x_a        = (const float*)d_in[0];
    const void*  edge_index =               d_in[1];
    const float* edge_attr  = (const float*)d_in[2];
    const float* g_w        = (const float*)d_in[3];
    const float* g_b        = (const float*)d_in[4];
    const float* f_w        = (const float*)d_in[5];
    const float* f_b        = (const float*)d_in[6];
    const float* cls_w      = (const float*)d_in[7];
    const float* cls_b      = (const float*)d_in[8];
    float* out = (float*)d_out;

    const int       N = in_sizes[0] / C;        // 20000
    const long long E = (long long)in_sizes[2]; // 640000
    const int twopart = (out_size >= 2 * N) ? 1 : 0;
    const int smem = N * (int)sizeof(float);    // 78.1 KB for N=20000

    static int smem_set = 0;
    if (!smem_set) {
        cudaFuncSetAttribute(edgeout_kernel,
                             cudaFuncAttributeMaxDynamicSharedMemorySize,
                             smem);
        smem_set = 1;
    }

    setup_kernel<<<1, 1024>>>(g_w, g_b, f_w, f_b, cls_w, cls_b);

    const int nblk_t = (N * 32 + 255) / 256;    // one warp per node
    t_kernel<<<nblk_t, 256>>>(x_a, N);

    edgeout_kernel<<<EO_NBLK, EO_NTHR, smem>>>(edge_index, edge_attr, out,
                                               N, E, twopart);
}